// round 9
// baseline (speedup 1.0000x reference)
#include <cuda_runtime.h>
#include <math.h>
#include <stdint.h>

// Problem constants
#define N_B     32
#define C_DIM   384
#define HW      3136        // 56*56
#define M_DIM   8
#define D_MODEL 768
#define E_DIM   768         // 2*C
#define KV_N    (M_DIM * E_DIM)   // 6144 per batch

// ---------------- device scratch -----------------------------------------------
#define NSPLIT 8
__device__ __align__(16) float g_kvp[NSPLIT * N_B * KV_N]; // raw GEMM partials

// ================= Kernel 1: split-K GEMM partials (measured ~18us) ============
#define BM 32
#define BN 64
#define BK 32
#define DSPL (D_MODEL / NSPLIT)   // 96

__global__ __launch_bounds__(256) void kvp_kernel(
    const float* __restrict__ gf,
    const float* __restrict__ W)
{
    __shared__ float As[BK][BM + 2];
    __shared__ float Bs[BK][BN + 4];

    const int tid = threadIdx.x;
    const int tx  = tid & 15;
    const int ty  = tid >> 4;
    const int eb  = blockIdx.x * BN;
    const int rb  = blockIdx.y * BM;
    const int s   = blockIdx.z;

    float acc[2][4];
    #pragma unroll
    for (int i = 0; i < 2; i++)
        #pragma unroll
        for (int j = 0; j < 4; j++) acc[i][j] = 0.f;

    for (int kb = s * DSPL; kb < (s + 1) * DSPL; kb += BK) {
        #pragma unroll
        for (int i = 0; i < 4; i++) {
            int idx = tid + i * 256;
            int r  = idx >> 5;
            int kk = idx & 31;
            As[kk][r] = gf[(size_t)(rb + r) * D_MODEL + kb + kk];
        }
        #pragma unroll
        for (int i = 0; i < 8; i++) {
            int idx = tid + i * 256;
            int e  = idx >> 5;
            int kk = idx & 31;
            Bs[kk][e] = W[(size_t)(eb + e) * D_MODEL + kb + kk];
        }
        __syncthreads();

        #pragma unroll
        for (int kk = 0; kk < BK; kk++) {
            float2 av = *(const float2*)&As[kk][ty * 2];
            float4 bv = *(const float4*)&Bs[kk][tx * 4];
            acc[0][0] += av.x * bv.x; acc[0][1] += av.x * bv.y;
            acc[0][2] += av.x * bv.z; acc[0][3] += av.x * bv.w;
            acc[1][0] += av.y * bv.x; acc[1][1] += av.y * bv.y;
            acc[1][2] += av.y * bv.z; acc[1][3] += av.y * bv.w;
        }
        __syncthreads();
    }

    float* dst = g_kvp + (size_t)s * (N_B * KV_N);
    #pragma unroll
    for (int r = 0; r < 2; r++) {
        float4 o = make_float4(acc[r][0], acc[r][1], acc[r][2], acc[r][3]);
        *(float4*)&dst[(size_t)(rb + ty * 2 + r) * E_DIM + eb + tx * 4] = o;
    }
}

// ================= Kernel 2: persistent attention, 28 warps/SM ==================
#define TILE_P   28
#define NTH      448                       // 14 warps; 2 CTAs/SM -> 28 warps
#define TPB      (HW / TILE_P)             // 112 tiles per batch
#define NTILES   (TPB * N_B)               // 3584

// xs buffer: [q 0..7][c' 0..47][px 0..27] ; QSTR mod 32 = 4 -> q-blocks bank-spread
#define QSTR     1348
#define XBUF     (8 * QSTR)                // 10784 words (43.1 KB)
#define KROW     432                       // K rows: even 4-wf LDS.128 (see bank math)
#define OFF_XS0  0
#define OFF_XS1  10784
#define OFF_KS   21568
#define OFF_VS   (OFF_KS + 8 * KROW)       // 25024 ; V: [k][c] rows of 384
#define OFF_SC   (OFF_VS + 8 * 384)        // 28096
#define OFF_AT   (OFF_SC + TILE_P * 8)     // 28320
#define SM_WORDS (OFF_AT + TILE_P * 8)     // 28544
#define SM_BYTES (SM_WORDS * 4)            // 114176 -> 2 CTAs/SM

__device__ __forceinline__ void issue_tile_loads(
    const float* __restrict__ x, int t, float* buf, int tid)
{
    const int n  = t / TPB;
    const int p0 = (t - n * TPB) * TILE_P;
    const float* xb = x + (size_t)n * C_DIM * HW + p0;
    #pragma unroll
    for (int tt = 0; tt < 6; tt++) {               // 2688 float4 / 448 thr
        int i  = tid + tt * NTH;
        int c  = i / 7;                            // 7 float4 per channel row
        int j  = i - c * 7;
        int q  = c / 48;
        int cp = c - q * 48;
        uint32_t dst = (uint32_t)__cvta_generic_to_shared(buf + q * QSTR + cp * TILE_P + j * 4);
        const float* src = xb + (size_t)c * HW + j * 4;
        asm volatile("cp.async.cg.shared.global [%0], [%1], 16;\n" :: "r"(dst), "l"(src));
    }
    asm volatile("cp.async.commit_group;\n");
}

__device__ __forceinline__ void stage_kv(
    int n, const float* __restrict__ bias, float* Ks, float* Vs, int tid)
{
    const float4* pp = (const float4*)g_kvp;
    const float4* b4 = (const float4*)bias;
    const int base = n * (KV_N / 4);
    for (int i = tid; i < KV_N / 4; i += NTH) {    // 1536 float4
        float4 s0 = pp[0 * 49152 + base + i];
        float4 s1 = pp[1 * 49152 + base + i];
        float4 s2 = pp[2 * 49152 + base + i];
        float4 s3 = pp[3 * 49152 + base + i];
        float4 s4 = pp[4 * 49152 + base + i];
        float4 s5 = pp[5 * 49152 + base + i];
        float4 s6 = pp[6 * 49152 + base + i];
        float4 s7 = pp[7 * 49152 + base + i];
        int m = i / 192;
        int j = i - m * 192;
        float4 bb = b4[j];
        float4 o;
        o.x = fminf(fmaxf(s0.x+s1.x+s2.x+s3.x+s4.x+s5.x+s6.x+s7.x + bb.x, 0.f), 6.f);
        o.y = fminf(fmaxf(s0.y+s1.y+s2.y+s3.y+s4.y+s5.y+s6.y+s7.y + bb.y, 0.f), 6.f);
        o.z = fminf(fmaxf(s0.z+s1.z+s2.z+s3.z+s4.z+s5.z+s6.z+s7.z + bb.z, 0.f), 6.f);
        o.w = fminf(fmaxf(s0.w+s1.w+s2.w+s3.w+s4.w+s5.w+s6.w+s7.w + bb.w, 0.f), 6.f);
        int e = j * 4;
        if (e < C_DIM) {
            int q = e / 48, cp = e - q * 48;
            *(float4*)&Ks[m * KROW + q * 52 + cp] = o;
        } else {
            *(float4*)&Vs[m * 384 + (e - C_DIM)] = o;
        }
    }
}

__global__ __launch_bounds__(NTH, 2) void attn_persist(
    const float* __restrict__ x,
    const float* __restrict__ bias,
    float* __restrict__ out)
{
    extern __shared__ float sm[];
    float* xsb[2] = { sm + OFF_XS0, sm + OFF_XS1 };
    float* Ks     = sm + OFF_KS;
    float* Vs     = sm + OFF_VS;
    float* scores = sm + OFF_SC;
    float* attnw  = sm + OFF_AT;

    const int tid = threadIdx.x;
    const int G   = gridDim.x;
    const int cta = blockIdx.x;

    const int T = NTILES / G;
    const int R = NTILES % G;
    const int t0  = cta * T + (cta < R ? cta : R);
    const int cnt = T + (cta < R ? 1 : 0);
    if (cnt == 0) return;

    int curn = -1;

    issue_tile_loads(x, t0, xsb[0], tid);

    for (int j = 0; j < cnt; j++) {
        const int t  = t0 + j;
        const int n  = t / TPB;
        const int p0 = (t - n * TPB) * TILE_P;
        float* buf = xsb[j & 1];

        if (j + 1 < cnt) {
            issue_tile_loads(x, t + 1, xsb[(j + 1) & 1], tid);
            asm volatile("cp.async.wait_group 1;\n");
        } else {
            asm volatile("cp.async.wait_group 0;\n");
        }

        if (n != curn) {
            stage_kv(n, bias, Ks, Vs, tid);
            curn = n;
        }
        __syncthreads();               // (1) buf + KV ready

        // ---------- phase 1: scores (warp = khalf x 4px ; lane = kg x q) -------
        {
            const int w     = tid >> 5;        // 0..13
            const int lane  = tid & 31;
            const int khalf = w / 7;           // 0..1
            const int pg    = w - khalf * 7;   // 0..6 -> px pg*4..+3
            const int kg    = lane >> 3;       // 0..3
            const int q     = lane & 7;        // 0..7
            const int k     = khalf * 4 + kg;
            const float* Kq = Ks + k * KROW + q * 52;
            const float* xq = buf + q * QSTR + pg * 4;

            float acc[4] = {0.f, 0.f, 0.f, 0.f};
            #pragma unroll 4
            for (int i4 = 0; i4 < 12; i4++) {
                float4 kk = *(const float4*)(Kq + i4 * 4);
                float kv[4] = {kk.x, kk.y, kk.z, kk.w};
                #pragma unroll
                for (int cc = 0; cc < 4; cc++) {
                    float4 xv = *(const float4*)(xq + (i4 * 4 + cc) * TILE_P);
                    acc[0] += xv.x * kv[cc]; acc[1] += xv.y * kv[cc];
                    acc[2] += xv.z * kv[cc]; acc[3] += xv.w * kv[cc];
                }
            }
            // reduce over q (octet butterfly)
            #pragma unroll
            for (int off = 1; off < 8; off <<= 1) {
                #pragma unroll
                for (int pp = 0; pp < 4; pp++)
                    acc[pp] += __shfl_xor_sync(0xffffffffu, acc[pp], off);
            }
            if (q == 0) {
                #pragma unroll
                for (int pp = 0; pp < 4; pp++)
                    scores[(pg * 4 + pp) * 8 + k] = acc[pp];
            }
        }
        __syncthreads();               // (2) scores ready

        // ---------- softmax over k=8 ----------
        if (tid < TILE_P) {
            float4 u0 = *(const float4*)&scores[tid * 8];
            float4 u1 = *(const float4*)&scores[tid * 8 + 4];
            float s[8] = {u0.x, u0.y, u0.z, u0.w, u1.x, u1.y, u1.z, u1.w};
            float mx = s[0];
            #pragma unroll
            for (int k = 1; k < 8; k++) mx = fmaxf(mx, s[k]);
            float sum = 0.f;
            #pragma unroll
            for (int k = 0; k < 8; k++) { s[k] = __expf(s[k] - mx); sum += s[k]; }
            float inv = 1.0f / sum;
            *(float4*)&attnw[tid * 8]     = make_float4(s[0]*inv, s[1]*inv, s[2]*inv, s[3]*inv);
            *(float4*)&attnw[tid * 8 + 4] = make_float4(s[4]*inv, s[5]*inv, s[6]*inv, s[7]*inv);
        }
        __syncthreads();               // (3) attnw ready

        // ---------- phase 2: out = x + attn @ V (12 ch x 2 px / thread) --------
        {
            const int cg  = tid / 14;          // 0..31 -> 12 channels
            const int pg2 = tid - cg * 14;     // 0..13 -> 2 pixels
            const int px  = pg2 * 2;

            float a[2][8];
            {
                float4 u0 = *(const float4*)&attnw[px * 8];
                float4 u1 = *(const float4*)&attnw[px * 8 + 4];
                float4 v0 = *(const float4*)&attnw[(px + 1) * 8];
                float4 v1 = *(const float4*)&attnw[(px + 1) * 8 + 4];
                a[0][0]=u0.x; a[0][1]=u0.y; a[0][2]=u0.z; a[0][3]=u0.w;
                a[0][4]=u1.x; a[0][5]=u1.y; a[0][6]=u1.z; a[0][7]=u1.w;
                a[1][0]=v0.x; a[1][1]=v0.y; a[1][2]=v0.z; a[1][3]=v0.w;
                a[1][4]=v1.x; a[1][5]=v1.y; a[1][6]=v1.z; a[1][7]=v1.w;
            }

            float* op = out + (size_t)n * C_DIM * HW + p0 + px;
            #pragma unroll
            for (int jj4 = 0; jj4 < 3; jj4++) {
                int c4 = cg * 12 + jj4 * 4;          // 4 consecutive channels
                int q  = c4 / 48;
                int cp = c4 - q * 48;
                const float* xb2 = buf + q * QSTR + cp * TILE_P + px;

                float o[4][2];
                #pragma unroll
                for (int cc = 0; cc < 4; cc++) {
                    float2 xv = *(const float2*)(xb2 + cc * TILE_P);
                    o[cc][0] = xv.x; o[cc][1] = xv.y;
                }
                #pragma unroll
                for (int k = 0; k < 8; k++) {
                    float4 vv = *(const float4*)&Vs[k * 384 + c4];  // broadcast-ish
                    o[0][0] += a[0][k] * vv.x; o[0][1] += a[1][k] * vv.x;
                    o[1][0] += a[0][k] * vv.y; o[1][1] += a[1][k] * vv.y;
                    o[2][0] += a[0][k] * vv.z; o[2][1] += a[1][k] * vv.z;
                    o[3][0] += a[0][k] * vv.w; o[3][1] += a[1][k] * vv.w;
                }
                #pragma unroll
                for (int cc = 0; cc < 4; cc++)
                    *(float2*)(op + (size_t)(c4 + cc) * HW) = make_float2(o[cc][0], o[cc][1]);
            }
        }
        __syncthreads();               // (4) buf reads done before next overwrite
    }
}

// ================= launch ======================================================
extern "C" void kernel_launch(void* const* d_in, const int* in_sizes, int n_in,
                              void* d_out, int out_size)
{
    const float* x  = (const float*)d_in[0];
    const float* gf = (const float*)d_in[1];
    const float* W  = (const float*)d_in[2];
    const float* b  = (const float*)d_in[3];
    float* out = (float*)d_out;

    kvp_kernel<<<dim3(E_DIM / BN, (N_B * M_DIM) / BM, NSPLIT), 256>>>(gf, W);

    int nsm = 0;
    cudaDeviceGetAttribute(&nsm, cudaDevAttrMultiProcessorCount, 0);
    if (nsm <= 0) nsm = 148;
    int grid = 2 * nsm;
    if (grid > NTILES) grid = NTILES;

    cudaFuncSetAttribute(attn_persist, cudaFuncAttributeMaxDynamicSharedMemorySize, SM_BYTES);
    attn_persist<<<grid, NTH, SM_BYTES>>>(x, b, out);
}

// round 10
// speedup vs baseline: 1.0019x; 1.0019x over previous
#include <cuda_runtime.h>
#include <math.h>
#include <stdint.h>

// Problem constants
#define N_B     32
#define C_DIM   384
#define HW      3136        // 56*56
#define M_DIM   8
#define D_MODEL 768
#define E_DIM   768         // 2*C
#define KV_N    (M_DIM * E_DIM)   // 6144 per batch

// ---------------- device scratch -----------------------------------------------
#define NSPLIT 8
__device__ __align__(16) float g_kvp[NSPLIT * N_B * KV_N]; // raw GEMM partials

// ================= Kernel 1: split-K GEMM partials (measured ~18us) ============
#define BM 32
#define BN 64
#define BK 32
#define DSPL (D_MODEL / NSPLIT)   // 96

__global__ __launch_bounds__(256) void kvp_kernel(
    const float* __restrict__ gf,
    const float* __restrict__ W)
{
    __shared__ float As[BK][BM + 2];
    __shared__ float Bs[BK][BN + 4];

    const int tid = threadIdx.x;
    const int tx  = tid & 15;
    const int ty  = tid >> 4;
    const int eb  = blockIdx.x * BN;
    const int rb  = blockIdx.y * BM;
    const int s   = blockIdx.z;

    float acc[2][4];
    #pragma unroll
    for (int i = 0; i < 2; i++)
        #pragma unroll
        for (int j = 0; j < 4; j++) acc[i][j] = 0.f;

    for (int kb = s * DSPL; kb < (s + 1) * DSPL; kb += BK) {
        #pragma unroll
        for (int i = 0; i < 4; i++) {
            int idx = tid + i * 256;
            int r  = idx >> 5;
            int kk = idx & 31;
            As[kk][r] = gf[(size_t)(rb + r) * D_MODEL + kb + kk];
        }
        #pragma unroll
        for (int i = 0; i < 8; i++) {
            int idx = tid + i * 256;
            int e  = idx >> 5;
            int kk = idx & 31;
            Bs[kk][e] = W[(size_t)(eb + e) * D_MODEL + kb + kk];
        }
        __syncthreads();

        #pragma unroll
        for (int kk = 0; kk < BK; kk++) {
            float2 av = *(const float2*)&As[kk][ty * 2];
            float4 bv = *(const float4*)&Bs[kk][tx * 4];
            acc[0][0] += av.x * bv.x; acc[0][1] += av.x * bv.y;
            acc[0][2] += av.x * bv.z; acc[0][3] += av.x * bv.w;
            acc[1][0] += av.y * bv.x; acc[1][1] += av.y * bv.y;
            acc[1][2] += av.y * bv.z; acc[1][3] += av.y * bv.w;
        }
        __syncthreads();
    }

    float* dst = g_kvp + (size_t)s * (N_B * KV_N);
    #pragma unroll
    for (int r = 0; r < 2; r++) {
        float4 o = make_float4(acc[r][0], acc[r][1], acc[r][2], acc[r][3]);
        *(float4*)&dst[(size_t)(rb + ty * 2 + r) * E_DIM + eb + tx * 4] = o;
    }
}

// ================= Kernel 2: persistent attention, 28 warps/SM ==================
#define TILE_P   28
#define NTH      448                       // 14 warps; 2 CTAs/SM -> 28 warps
#define TPB      (HW / TILE_P)             // 112 tiles per batch
#define NTILES   (TPB * N_B)               // 3584

// xs buffer: [q 0..7][c' 0..47][px 0..27] ; QSTR mod 32 = 4 -> q-blocks bank-spread
#define QSTR     1348
#define XBUF     (8 * QSTR)                // 10784 words (43.1 KB)
#define KROW     432                       // K rows: even 4-wf LDS.128 (see bank math)
#define OFF_XS0  0
#define OFF_XS1  10784
#define OFF_KS   21568
#define OFF_VS   (OFF_KS + 8 * KROW)       // 25024 ; V: [k][c] rows of 384
#define OFF_SC   (OFF_VS + 8 * 384)        // 28096
#define OFF_AT   (OFF_SC + TILE_P * 8)     // 28320
#define SM_WORDS (OFF_AT + TILE_P * 8)     // 28544
#define SM_BYTES (SM_WORDS * 4)            // 114176 -> 2 CTAs/SM

__device__ __forceinline__ void issue_tile_loads(
    const float* __restrict__ x, int t, float* buf, int tid)
{
    const int n  = t / TPB;
    const int p0 = (t - n * TPB) * TILE_P;
    const float* xb = x + (size_t)n * C_DIM * HW + p0;
    #pragma unroll
    for (int tt = 0; tt < 6; tt++) {               // 2688 float4 / 448 thr
        int i  = tid + tt * NTH;
        int c  = i / 7;                            // 7 float4 per channel row
        int j  = i - c * 7;
        int q  = c / 48;
        int cp = c - q * 48;
        uint32_t dst = (uint32_t)__cvta_generic_to_shared(buf + q * QSTR + cp * TILE_P + j * 4);
        const float* src = xb + (size_t)c * HW + j * 4;
        asm volatile("cp.async.cg.shared.global [%0], [%1], 16;\n" :: "r"(dst), "l"(src));
    }
    asm volatile("cp.async.commit_group;\n");
}

__device__ __forceinline__ void stage_kv(
    int n, const float* __restrict__ bias, float* Ks, float* Vs, int tid)
{
    const float4* pp = (const float4*)g_kvp;
    const float4* b4 = (const float4*)bias;
    const int base = n * (KV_N / 4);
    for (int i = tid; i < KV_N / 4; i += NTH) {    // 1536 float4
        float4 s0 = pp[0 * 49152 + base + i];
        float4 s1 = pp[1 * 49152 + base + i];
        float4 s2 = pp[2 * 49152 + base + i];
        float4 s3 = pp[3 * 49152 + base + i];
        float4 s4 = pp[4 * 49152 + base + i];
        float4 s5 = pp[5 * 49152 + base + i];
        float4 s6 = pp[6 * 49152 + base + i];
        float4 s7 = pp[7 * 49152 + base + i];
        int m = i / 192;
        int j = i - m * 192;
        float4 bb = b4[j];
        float4 o;
        o.x = fminf(fmaxf(s0.x+s1.x+s2.x+s3.x+s4.x+s5.x+s6.x+s7.x + bb.x, 0.f), 6.f);
        o.y = fminf(fmaxf(s0.y+s1.y+s2.y+s3.y+s4.y+s5.y+s6.y+s7.y + bb.y, 0.f), 6.f);
        o.z = fminf(fmaxf(s0.z+s1.z+s2.z+s3.z+s4.z+s5.z+s6.z+s7.z + bb.z, 0.f), 6.f);
        o.w = fminf(fmaxf(s0.w+s1.w+s2.w+s3.w+s4.w+s5.w+s6.w+s7.w + bb.w, 0.f), 6.f);
        int e = j * 4;
        if (e < C_DIM) {
            int q = e / 48, cp = e - q * 48;
            *(float4*)&Ks[m * KROW + q * 52 + cp] = o;
        } else {
            *(float4*)&Vs[m * 384 + (e - C_DIM)] = o;
        }
    }
}

__global__ __launch_bounds__(NTH, 2) void attn_persist(
    const float* __restrict__ x,
    const float* __restrict__ bias,
    float* __restrict__ out)
{
    extern __shared__ float sm[];
    float* xsb[2] = { sm + OFF_XS0, sm + OFF_XS1 };
    float* Ks     = sm + OFF_KS;
    float* Vs     = sm + OFF_VS;
    float* scores = sm + OFF_SC;
    float* attnw  = sm + OFF_AT;

    const int tid = threadIdx.x;
    const int G   = gridDim.x;
    const int cta = blockIdx.x;

    const int T = NTILES / G;
    const int R = NTILES % G;
    const int t0  = cta * T + (cta < R ? cta : R);
    const int cnt = T + (cta < R ? 1 : 0);
    if (cnt == 0) return;

    int curn = -1;

    issue_tile_loads(x, t0, xsb[0], tid);

    for (int j = 0; j < cnt; j++) {
        const int t  = t0 + j;
        const int n  = t / TPB;
        const int p0 = (t - n * TPB) * TILE_P;
        float* buf = xsb[j & 1];

        if (j + 1 < cnt) {
            issue_tile_loads(x, t + 1, xsb[(j + 1) & 1], tid);
            asm volatile("cp.async.wait_group 1;\n");
        } else {
            asm volatile("cp.async.wait_group 0;\n");
        }

        if (n != curn) {
            stage_kv(n, bias, Ks, Vs, tid);
            curn = n;
        }
        __syncthreads();               // (1) buf + KV ready

        // ---------- phase 1: scores (warp = khalf x 4px ; lane = kg x q) -------
        {
            const int w     = tid >> 5;        // 0..13
            const int lane  = tid & 31;
            const int khalf = w / 7;           // 0..1
            const int pg    = w - khalf * 7;   // 0..6 -> px pg*4..+3
            const int kg    = lane >> 3;       // 0..3
            const int q     = lane & 7;        // 0..7
            const int k     = khalf * 4 + kg;
            const float* Kq = Ks + k * KROW + q * 52;
            const float* xq = buf + q * QSTR + pg * 4;

            float acc[4] = {0.f, 0.f, 0.f, 0.f};
            #pragma unroll 4
            for (int i4 = 0; i4 < 12; i4++) {
                float4 kk = *(const float4*)(Kq + i4 * 4);
                float kv[4] = {kk.x, kk.y, kk.z, kk.w};
                #pragma unroll
                for (int cc = 0; cc < 4; cc++) {
                    float4 xv = *(const float4*)(xq + (i4 * 4 + cc) * TILE_P);
                    acc[0] += xv.x * kv[cc]; acc[1] += xv.y * kv[cc];
                    acc[2] += xv.z * kv[cc]; acc[3] += xv.w * kv[cc];
                }
            }
            // reduce over q (octet butterfly)
            #pragma unroll
            for (int off = 1; off < 8; off <<= 1) {
                #pragma unroll
                for (int pp = 0; pp < 4; pp++)
                    acc[pp] += __shfl_xor_sync(0xffffffffu, acc[pp], off);
            }
            if (q == 0) {
                #pragma unroll
                for (int pp = 0; pp < 4; pp++)
                    scores[(pg * 4 + pp) * 8 + k] = acc[pp];
            }
        }
        __syncthreads();               // (2) scores ready

        // ---------- softmax over k=8 ----------
        if (tid < TILE_P) {
            float4 u0 = *(const float4*)&scores[tid * 8];
            float4 u1 = *(const float4*)&scores[tid * 8 + 4];
            float s[8] = {u0.x, u0.y, u0.z, u0.w, u1.x, u1.y, u1.z, u1.w};
            float mx = s[0];
            #pragma unroll
            for (int k = 1; k < 8; k++) mx = fmaxf(mx, s[k]);
            float sum = 0.f;
            #pragma unroll
            for (int k = 0; k < 8; k++) { s[k] = __expf(s[k] - mx); sum += s[k]; }
            float inv = 1.0f / sum;
            *(float4*)&attnw[tid * 8]     = make_float4(s[0]*inv, s[1]*inv, s[2]*inv, s[3]*inv);
            *(float4*)&attnw[tid * 8 + 4] = make_float4(s[4]*inv, s[5]*inv, s[6]*inv, s[7]*inv);
        }
        __syncthreads();               // (3) attnw ready

        // ---------- phase 2: out = x + attn @ V (12 ch x 2 px / thread) --------
        {
            const int cg  = tid / 14;          // 0..31 -> 12 channels
            const int pg2 = tid - cg * 14;     // 0..13 -> 2 pixels
            const int px  = pg2 * 2;

            float a[2][8];
            {
                float4 u0 = *(const float4*)&attnw[px * 8];
                float4 u1 = *(const float4*)&attnw[px * 8 + 4];
                float4 v0 = *(const float4*)&attnw[(px + 1) * 8];
                float4 v1 = *(const float4*)&attnw[(px + 1) * 8 + 4];
                a[0][0]=u0.x; a[0][1]=u0.y; a[0][2]=u0.z; a[0][3]=u0.w;
                a[0][4]=u1.x; a[0][5]=u1.y; a[0][6]=u1.z; a[0][7]=u1.w;
                a[1][0]=v0.x; a[1][1]=v0.y; a[1][2]=v0.z; a[1][3]=v0.w;
                a[1][4]=v1.x; a[1][5]=v1.y; a[1][6]=v1.z; a[1][7]=v1.w;
            }

            float* op = out + (size_t)n * C_DIM * HW + p0 + px;
            #pragma unroll
            for (int jj4 = 0; jj4 < 3; jj4++) {
                int c4 = cg * 12 + jj4 * 4;          // 4 consecutive channels
                int q  = c4 / 48;
                int cp = c4 - q * 48;
                const float* xb2 = buf + q * QSTR + cp * TILE_P + px;

                float o[4][2];
                #pragma unroll
                for (int cc = 0; cc < 4; cc++) {
                    float2 xv = *(const float2*)(xb2 + cc * TILE_P);
                    o[cc][0] = xv.x; o[cc][1] = xv.y;
                }
                #pragma unroll
                for (int k = 0; k < 8; k++) {
                    float4 vv = *(const float4*)&Vs[k * 384 + c4];  // broadcast-ish
                    o[0][0] += a[0][k] * vv.x; o[0][1] += a[1][k] * vv.x;
                    o[1][0] += a[0][k] * vv.y; o[1][1] += a[1][k] * vv.y;
                    o[2][0] += a[0][k] * vv.z; o[2][1] += a[1][k] * vv.z;
                    o[3][0] += a[0][k] * vv.w; o[3][1] += a[1][k] * vv.w;
                }
                #pragma unroll
                for (int cc = 0; cc < 4; cc++)
                    *(float2*)(op + (size_t)(c4 + cc) * HW) = make_float2(o[cc][0], o[cc][1]);
            }
        }
        __syncthreads();               // (4) buf reads done before next overwrite
    }
}

// ================= launch ======================================================
extern "C" void kernel_launch(void* const* d_in, const int* in_sizes, int n_in,
                              void* d_out, int out_size)
{
    const float* x  = (const float*)d_in[0];
    const float* gf = (const float*)d_in[1];
    const float* W  = (const float*)d_in[2];
    const float* b  = (const float*)d_in[3];
    float* out = (float*)d_out;

    kvp_kernel<<<dim3(E_DIM / BN, (N_B * M_DIM) / BM, NSPLIT), 256>>>(gf, W);

    int nsm = 0;
    cudaDeviceGetAttribute(&nsm, cudaDevAttrMultiProcessorCount, 0);
    if (nsm <= 0) nsm = 148;
    int grid = 2 * nsm;
    if (grid > NTILES) grid = NTILES;

    cudaFuncSetAttribute(attn_persist, cudaFuncAttributeMaxDynamicSharedMemorySize, SM_BYTES);
    attn_persist<<<grid, NTH, SM_BYTES>>>(x, b, out);
}

// round 11
// speedup vs baseline: 1.5189x; 1.5161x over previous
#include <cuda_runtime.h>
#include <math.h>
#include <stdint.h>

// Problem constants
#define N_B     32
#define C_DIM   384
#define HW      3136        // 56*56
#define M_DIM   8
#define D_MODEL 768
#define E_DIM   768         // 2*C
#define KV_N    (M_DIM * E_DIM)   // 6144 per batch

// ---------------- device scratch -----------------------------------------------
#define NSPLIT 8
__device__ __align__(16) float g_kvp[NSPLIT * N_B * KV_N]; // raw GEMM partials
__device__ __align__(16) float g_kv [N_B * KV_N];          // combined clipped KV

// ================= Kernel 1: split-K GEMM partials ==============================
#define BM 32
#define BN 64
#define BK 32
#define DSPL (D_MODEL / NSPLIT)   // 96

__global__ __launch_bounds__(256) void kvp_kernel(
    const float* __restrict__ gf,
    const float* __restrict__ W)
{
    __shared__ float As[BK][BM + 2];
    __shared__ float Bs[BK][BN + 4];

    const int tid = threadIdx.x;
    const int tx  = tid & 15;
    const int ty  = tid >> 4;
    const int eb  = blockIdx.x * BN;
    const int rb  = blockIdx.y * BM;
    const int s   = blockIdx.z;

    float acc[2][4];
    #pragma unroll
    for (int i = 0; i < 2; i++)
        #pragma unroll
        for (int j = 0; j < 4; j++) acc[i][j] = 0.f;

    for (int kb = s * DSPL; kb < (s + 1) * DSPL; kb += BK) {
        #pragma unroll
        for (int i = 0; i < 4; i++) {
            int idx = tid + i * 256;
            int r  = idx >> 5;
            int kk = idx & 31;
            As[kk][r] = gf[(size_t)(rb + r) * D_MODEL + kb + kk];
        }
        #pragma unroll
        for (int i = 0; i < 8; i++) {
            int idx = tid + i * 256;
            int e  = idx >> 5;
            int kk = idx & 31;
            Bs[kk][e] = W[(size_t)(eb + e) * D_MODEL + kb + kk];
        }
        __syncthreads();

        #pragma unroll
        for (int kk = 0; kk < BK; kk++) {
            float2 av = *(const float2*)&As[kk][ty * 2];
            float4 bv = *(const float4*)&Bs[kk][tx * 4];
            acc[0][0] += av.x * bv.x; acc[0][1] += av.x * bv.y;
            acc[0][2] += av.x * bv.z; acc[0][3] += av.x * bv.w;
            acc[1][0] += av.y * bv.x; acc[1][1] += av.y * bv.y;
            acc[1][2] += av.y * bv.z; acc[1][3] += av.y * bv.w;
        }
        __syncthreads();
    }

    float* dst = g_kvp + (size_t)s * (N_B * KV_N);
    #pragma unroll
    for (int r = 0; r < 2; r++) {
        float4 o = make_float4(acc[r][0], acc[r][1], acc[r][2], acc[r][3]);
        *(float4*)&dst[(size_t)(rb + ty * 2 + r) * E_DIM + eb + tx * 4] = o;
    }
}

// ================= Kernel 1b: combine partials + bias + clip ====================
__global__ __launch_bounds__(512) void kv_combine_kernel(const float* __restrict__ bias)
{
    const int idx = blockIdx.x * 512 + threadIdx.x;   // 49152 float4 total
    const float4* p = (const float4*)g_kvp;
    float4 a = p[idx];
    #pragma unroll
    for (int s = 1; s < NSPLIT; s++) {
        float4 v = p[(size_t)s * 49152 + idx];
        a.x += v.x; a.y += v.y; a.z += v.z; a.w += v.w;
    }
    float4 bb = ((const float4*)bias)[idx % (E_DIM / 4)];
    float4 o;
    o.x = fminf(fmaxf(a.x + bb.x, 0.f), 6.f);
    o.y = fminf(fmaxf(a.y + bb.y, 0.f), 6.f);
    o.z = fminf(fmaxf(a.z + bb.z, 0.f), 6.f);
    o.w = fminf(fmaxf(a.w + bb.w, 0.f), 6.f);
    ((float4*)g_kv)[idx] = o;
}

// ================= Kernel 2: register-resident attention ========================
// CTA = 256 threads = 8 warps x 32 pixels. Warp q owns channels [48q, 48q+48).
// x lives in 48 registers per thread: gmem -> regs -> gmem, NO x smem traffic.
// K/V in smem, all accesses warp-broadcast (1 wavefront). Scores reduced via a
// tiny transposed part[] array; softmax by warp 0.
#define TILE_P 32
#define NTH2   256

// smem (floats): Ks 3072 | Vs 3072 | part 2048 | attnw 256
#define OFF_VS2  3072
#define OFF_PART 6144
#define OFF_AT2  8192
#define SM2_FLOATS 8448          // 33792 B

__global__ __launch_bounds__(NTH2, 3) void attn_reg(
    const float* __restrict__ x,
    float* __restrict__ out)
{
    __shared__ float smem2[SM2_FLOATS];
    float* Ks    = smem2;               // [k][c] rows of 384
    float* Vs    = smem2 + OFF_VS2;     // [k][c]
    float* part  = smem2 + OFF_PART;    // [q][k][p] : q*256 + k*32 + p
    float* attnw = smem2 + OFF_AT2;     // [k][p]    : k*32 + p

    const int tid = threadIdx.x;
    const int n   = blockIdx.y;
    const int p0  = blockIdx.x * TILE_P;
    const int q   = tid >> 5;           // warp id 0..7
    const int p   = tid & 31;           // lane = pixel

    // ---- load my 48 x values into registers (coalesced 128B warp loads) ----
    float xr[48];
    {
        const float* xb = x + ((size_t)n * C_DIM + q * 48) * HW + p0 + p;
        #pragma unroll
        for (int i = 0; i < 48; i++) xr[i] = __ldg(xb + (size_t)i * HW);
    }

    // ---- stage K,V into smem (1536 float4 / 256 thr = 6 each) ----
    {
        const float4* kv4 = (const float4*)g_kv + (size_t)n * (KV_N / 4);
        #pragma unroll
        for (int t = 0; t < 6; t++) {
            int i = tid + t * NTH2;
            float4 v = kv4[i];
            int m = i / 192;            // k row
            int j = i - m * 192;        // float4 within row
            int e = j * 4;
            if (e < C_DIM) *(float4*)&Ks[m * C_DIM + e] = v;
            else           *(float4*)&Vs[m * C_DIM + (e - C_DIM)] = v;
        }
    }
    __syncthreads();

    // ---- phase 1: partial scores over my 48 channels ----
    {
        float acc[8];
        #pragma unroll
        for (int k = 0; k < 8; k++) acc[k] = 0.f;

        const float* Kq = Ks + q * 48;
        #pragma unroll
        for (int i4 = 0; i4 < 12; i4++) {
            #pragma unroll
            for (int k = 0; k < 8; k++) {
                float4 kk = *(const float4*)(Kq + k * C_DIM + i4 * 4);  // broadcast
                acc[k] += xr[i4*4+0] * kk.x + xr[i4*4+1] * kk.y
                        + xr[i4*4+2] * kk.z + xr[i4*4+3] * kk.w;
            }
        }
        // transposed partial store: conflict-free scalar STS
        #pragma unroll
        for (int k = 0; k < 8; k++) part[q * 256 + k * 32 + p] = acc[k];
    }
    __syncthreads();

    // ---- reduce over q + softmax (warp 0) ----
    if (tid < 32) {
        float s[8];
        #pragma unroll
        for (int k = 0; k < 8; k++) {
            float v = 0.f;
            #pragma unroll
            for (int qq = 0; qq < 8; qq++) v += part[qq * 256 + k * 32 + tid];
            s[k] = v;
        }
        float mx = s[0];
        #pragma unroll
        for (int k = 1; k < 8; k++) mx = fmaxf(mx, s[k]);
        float sum = 0.f;
        #pragma unroll
        for (int k = 0; k < 8; k++) { s[k] = __expf(s[k] - mx); sum += s[k]; }
        float inv = 1.0f / sum;
        #pragma unroll
        for (int k = 0; k < 8; k++) attnw[k * 32 + tid] = s[k] * inv;
    }
    __syncthreads();

    // ---- phase 2: out = x + attn @ V (x from registers, coalesced stores) ----
    {
        float a[8];
        #pragma unroll
        for (int k = 0; k < 8; k++) a[k] = attnw[k * 32 + p];   // conflict-free

        const float* Vq = Vs + q * 48;
        float* op = out + ((size_t)n * C_DIM + q * 48) * HW + p0 + p;
        #pragma unroll
        for (int i4 = 0; i4 < 12; i4++) {
            float o0 = xr[i4*4+0], o1 = xr[i4*4+1], o2 = xr[i4*4+2], o3 = xr[i4*4+3];
            #pragma unroll
            for (int k = 0; k < 8; k++) {
                float4 vv = *(const float4*)(Vq + k * C_DIM + i4 * 4);  // broadcast
                o0 += a[k] * vv.x; o1 += a[k] * vv.y;
                o2 += a[k] * vv.z; o3 += a[k] * vv.w;
            }
            op[(size_t)(i4*4+0) * HW] = o0;
            op[(size_t)(i4*4+1) * HW] = o1;
            op[(size_t)(i4*4+2) * HW] = o2;
            op[(size_t)(i4*4+3) * HW] = o3;
        }
    }
}

// ================= launch ======================================================
extern "C" void kernel_launch(void* const* d_in, const int* in_sizes, int n_in,
                              void* d_out, int out_size)
{
    const float* x  = (const float*)d_in[0];
    const float* gf = (const float*)d_in[1];
    const float* W  = (const float*)d_in[2];
    const float* b  = (const float*)d_in[3];
    float* out = (float*)d_out;

    kvp_kernel<<<dim3(E_DIM / BN, (N_B * M_DIM) / BM, NSPLIT), 256>>>(gf, W);
    kv_combine_kernel<<<(N_B * KV_N / 4) / 512, 512>>>(b);

    attn_reg<<<dim3(HW / TILE_P, N_B), NTH2>>>(x, out);
}